// round 5
// baseline (speedup 1.0000x reference)
#include <cuda_runtime.h>
#include <cstdint>

// Shapes (fixed for this problem)
#define M_TOK 8192   // B*C tokens
#define Dm    512    // d_model
#define Kcb   8192   // codebook size
#define Ff    129    // stft bins
#define Cc    64     // channels (for pos_emb)

// Main-kernel tiling
#define NSPLIT  4        // K split across blockIdx.y
#define KSPL    (Kcb / NSPLIT)   // 2048 codes per split
#define MT      128      // token tile
#define NT      128      // code tile (chunk)
#define DC      16       // depth (d) per smem stage
#define KCHUNKS (KSPL / NT)      // 16 chunks per split
#define NDST    (Dm / DC)        // 32 depth stages

// -------- scratch (static device globals: no runtime allocation) --------
__device__ float g_z[M_TOK * Dm];          // projected tokens  (16 MB)
__device__ float g_e2[Kcb];                // |e_k|^2
__device__ float g_pmin[NSPLIT * M_TOK];   // per-split partial min score
__device__ int   g_pidx[NSPLIT * M_TOK];   // per-split partial argmin
__device__ float g_loss;                   // commit-loss accumulator

// packed fp32x2 FMA (sm_100+): d.lo += a.lo*b.lo ; d.hi += a.hi*b.hi
#define FMA2(accv, av, bv) \
    asm("fma.rn.f32x2 %0, %1, %2, %0;" : "+l"(accv) : "l"(av), "l"(bv))

// ======================= kernel 1: e2 + zero loss =======================
__global__ __launch_bounds__(256) void k_e2(const float* __restrict__ cb) {
    int row  = blockIdx.x * 8 + (threadIdx.x >> 5);
    int lane = threadIdx.x & 31;
    const float* r = cb + row * Dm;
    float s = 0.f;
    #pragma unroll 4
    for (int i = lane; i < Dm; i += 32) { float v = r[i]; s = fmaf(v, v, s); }
    #pragma unroll
    for (int o = 16; o; o >>= 1) s += __shfl_xor_sync(0xffffffffu, s, o);
    if (lane == 0) g_e2[row] = s;
    if (blockIdx.x == 0 && threadIdx.x == 0) g_loss = 0.f;
}

// ======================= kernel 2: z = x @ W + b ========================
// One block = 32 tokens, 256 threads; thread t owns columns d=t and d=t+256.
__global__ __launch_bounds__(256) void k_zgemm(const float* __restrict__ x,
                                               const float* __restrict__ W,
                                               const float* __restrict__ b) {
    __shared__ float xs[32][Ff];
    const int m0 = blockIdx.x * 32;
    const int t  = threadIdx.x;

    for (int i = t; i < 32 * Ff; i += 256) {
        int r = i / Ff, c = i - r * Ff;
        xs[r][c] = x[(m0 + r) * Ff + c];
    }
    __syncthreads();

    float acc0[32], acc1[32];
    const float b0 = b[t], b1 = b[t + 256];
    #pragma unroll
    for (int i = 0; i < 32; i++) { acc0[i] = b0; acc1[i] = b1; }

    float w0 = W[t], w1 = W[t + 256];
    for (int f = 0; f < Ff; f++) {
        float nw0 = 0.f, nw1 = 0.f;
        if (f + 1 < Ff) { nw0 = W[(f + 1) * Dm + t]; nw1 = W[(f + 1) * Dm + t + 256]; }
        #pragma unroll
        for (int i = 0; i < 32; i++) {
            float xv = xs[i][f];
            acc0[i] = fmaf(xv, w0, acc0[i]);
            acc1[i] = fmaf(xv, w1, acc1[i]);
        }
        w0 = nw0; w1 = nw1;
    }
    #pragma unroll
    for (int i = 0; i < 32; i++) {
        g_z[(m0 + i) * Dm + t]       = acc0[i];
        g_z[(m0 + i) * Dm + t + 256] = acc1[i];
    }
}

// ============ kernel 3: fused dist-GEMM + running argmin ================
// Grid (M/MT, NSPLIT). Block 256 threads; micro-tile 8 tokens x 8 codes.
// z stored duplicated in SMEM as (z,z) pairs so FFMA2 lanes carry 2 codes.
__global__ __launch_bounds__(256, 2) void k_argmin(const float* __restrict__ cb) {
    __shared__ float Zs[2][DC][2 * MT];   // 32 KB (duplicated z)
    __shared__ float Cs[2][DC][NT];       // 16 KB

    const int t  = threadIdx.x;
    const int tx = t & 15;     // code group
    const int ty = t >> 4;     // token group
    const int m0  = blockIdx.x * MT;
    const int ks0 = blockIdx.y * KSPL;

    // fill-index precompute: two 512-float4 passes per stage
    const int rowA = t >> 2,         c4A = (t & 3) * 4;          // li = t
    const int rowB = (t + 256) >> 2, c4B = ((t + 256) & 3) * 4;  // li = t+256

    unsigned long long acc[8][4];
    float rmin[8]; int ridx[8];
    #pragma unroll
    for (int i = 0; i < 8; i++) { rmin[i] = __int_as_float(0x7f800000); ridx[i] = 0x7fffffff; }

    for (int ch = 0; ch < KCHUNKS; ch++) {
        const int n0 = ks0 + ch * NT;
        #pragma unroll
        for (int i = 0; i < 8; i++)
            #pragma unroll
            for (int j = 0; j < 4; j++) acc[i][j] = 0ull;

        // ---- prologue: fill stage 0 (d0 = 0) ----
        {
            float4 vzA = *(const float4*)&g_z[(m0 + rowA) * Dm + c4A];
            float4 vzB = *(const float4*)&g_z[(m0 + rowB) * Dm + c4B];
            float4 vcA = *(const float4*)&cb [(n0 + rowA) * Dm + c4A];
            float4 vcB = *(const float4*)&cb [(n0 + rowB) * Dm + c4B];
            Cs[0][c4A+0][rowA]=vcA.x; Cs[0][c4A+1][rowA]=vcA.y; Cs[0][c4A+2][rowA]=vcA.z; Cs[0][c4A+3][rowA]=vcA.w;
            Cs[0][c4B+0][rowB]=vcB.x; Cs[0][c4B+1][rowB]=vcB.y; Cs[0][c4B+2][rowB]=vcB.z; Cs[0][c4B+3][rowB]=vcB.w;
            *(float2*)&Zs[0][c4A+0][2*rowA] = make_float2(vzA.x, vzA.x);
            *(float2*)&Zs[0][c4A+1][2*rowA] = make_float2(vzA.y, vzA.y);
            *(float2*)&Zs[0][c4A+2][2*rowA] = make_float2(vzA.z, vzA.z);
            *(float2*)&Zs[0][c4A+3][2*rowA] = make_float2(vzA.w, vzA.w);
            *(float2*)&Zs[0][c4B+0][2*rowB] = make_float2(vzB.x, vzB.x);
            *(float2*)&Zs[0][c4B+1][2*rowB] = make_float2(vzB.y, vzB.y);
            *(float2*)&Zs[0][c4B+2][2*rowB] = make_float2(vzB.z, vzB.z);
            *(float2*)&Zs[0][c4B+3][2*rowB] = make_float2(vzB.w, vzB.w);
        }
        __syncthreads();

        // ---- mainloop over depth stages (double-buffered) ----
        for (int ds = 0; ds < NDST; ds++) {
            const int cur = ds & 1;
            float4 vzA, vzB, vcA, vcB;
            const bool pf = (ds + 1 < NDST);
            if (pf) {
                const int d0n = (ds + 1) * DC;
                vzA = *(const float4*)&g_z[(m0 + rowA) * Dm + d0n + c4A];
                vzB = *(const float4*)&g_z[(m0 + rowB) * Dm + d0n + c4B];
                vcA = *(const float4*)&cb [(n0 + rowA) * Dm + d0n + c4A];
                vcB = *(const float4*)&cb [(n0 + rowB) * Dm + d0n + c4B];
            }

            // compute 16 depth steps from stage `cur`
            #pragma unroll
            for (int kc = 0; kc < DC; kc++) {
                const ulonglong2* ap = (const ulonglong2*)&Zs[cur][kc][ty * 16];
                ulonglong2 a0 = ap[0], a1 = ap[1], a2 = ap[2], a3 = ap[3];
                const ulonglong2* bp = (const ulonglong2*)&Cs[cur][kc][tx * 8];
                ulonglong2 bb0 = bp[0], bb1 = bp[1];
                unsigned long long A[8] = {a0.x,a0.y,a1.x,a1.y,a2.x,a2.y,a3.x,a3.y};
                unsigned long long Bv[4] = {bb0.x,bb0.y,bb1.x,bb1.y};
                #pragma unroll
                for (int i = 0; i < 8; i++)
                    #pragma unroll
                    for (int j = 0; j < 4; j++)
                        FMA2(acc[i][j], A[i], Bv[j]);
            }

            if (pf) {
                const int nx = cur ^ 1;
                Cs[nx][c4A+0][rowA]=vcA.x; Cs[nx][c4A+1][rowA]=vcA.y; Cs[nx][c4A+2][rowA]=vcA.z; Cs[nx][c4A+3][rowA]=vcA.w;
                Cs[nx][c4B+0][rowB]=vcB.x; Cs[nx][c4B+1][rowB]=vcB.y; Cs[nx][c4B+2][rowB]=vcB.z; Cs[nx][c4B+3][rowB]=vcB.w;
                *(float2*)&Zs[nx][c4A+0][2*rowA] = make_float2(vzA.x, vzA.x);
                *(float2*)&Zs[nx][c4A+1][2*rowA] = make_float2(vzA.y, vzA.y);
                *(float2*)&Zs[nx][c4A+2][2*rowA] = make_float2(vzA.z, vzA.z);
                *(float2*)&Zs[nx][c4A+3][2*rowA] = make_float2(vzA.w, vzA.w);
                *(float2*)&Zs[nx][c4B+0][2*rowB] = make_float2(vzB.x, vzB.x);
                *(float2*)&Zs[nx][c4B+1][2*rowB] = make_float2(vzB.y, vzB.y);
                *(float2*)&Zs[nx][c4B+2][2*rowB] = make_float2(vzB.z, vzB.z);
                *(float2*)&Zs[nx][c4B+3][2*rowB] = make_float2(vzB.w, vzB.w);
            }
            __syncthreads();
        }

        // ---- epilogue: score = e2 - 2*dot, running argmin ----
        const int kb = n0 + tx * 8;
        #pragma unroll
        for (int i = 0; i < 8; i++) {
            #pragma unroll
            for (int j = 0; j < 4; j++) {
                float dlo = __uint_as_float((unsigned)(acc[i][j] & 0xffffffffull));
                float dhi = __uint_as_float((unsigned)(acc[i][j] >> 32));
                int k0 = kb + 2 * j;
                float s0 = fmaf(-2.f, dlo, g_e2[k0]);
                float s1 = fmaf(-2.f, dhi, g_e2[k0 + 1]);
                if (s0 < rmin[i] || (s0 == rmin[i] && k0     < ridx[i])) { rmin[i] = s0; ridx[i] = k0;     }
                if (s1 < rmin[i] || (s1 == rmin[i] && k0 + 1 < ridx[i])) { rmin[i] = s1; ridx[i] = k0 + 1; }
            }
        }
    }

    // ---- cross-thread (tx) reduction via smem reuse ----
    __syncthreads();
    float* smin = (float*)Zs;   // 128*16 floats
    int*   sidx = (int*)Cs;     // 128*16 ints
    #pragma unroll
    for (int i = 0; i < 8; i++) {
        int m = ty * 8 + i;
        smin[m * 16 + tx] = rmin[i];
        sidx[m * 16 + tx] = ridx[i];
    }
    __syncthreads();
    if (t < MT) {
        float bs = smin[t * 16]; int bi = sidx[t * 16];
        #pragma unroll
        for (int j = 1; j < 16; j++) {
            float s = smin[t * 16 + j]; int ix = sidx[t * 16 + j];
            if (s < bs || (s == bs && ix < bi)) { bs = s; bi = ix; }
        }
        g_pmin[blockIdx.y * M_TOK + m0 + t] = bs;
        g_pidx[blockIdx.y * M_TOK + m0 + t] = bi;
    }
}

// ======= kernel 4: combine splits, gather, out = q + pos, loss ==========
__global__ __launch_bounds__(256) void k_out(const float* __restrict__ cb,
                                             const float* __restrict__ pos,
                                             float* __restrict__ out) {
    const int m = blockIdx.x;
    const int t = threadIdx.x;
    __shared__ int sIdx;
    __shared__ float red[8];

    if (t == 0) {
        float bs = g_pmin[m]; int bi = g_pidx[m];
        #pragma unroll
        for (int p = 1; p < NSPLIT; p++) {
            float s = g_pmin[p * M_TOK + m]; int ix = g_pidx[p * M_TOK + m];
            if (s < bs || (s == bs && ix < bi)) { bs = s; bi = ix; }
        }
        sIdx = bi;
    }
    __syncthreads();
    const int idx = sIdx;
    const float* q  = cb  + (long)idx * Dm;
    const float* zr = g_z + (long)m   * Dm;
    const float* pr = pos + (m & (Cc - 1)) * Dm;

    float lsum = 0.f;
    #pragma unroll
    for (int r = 0; r < 2; r++) {
        int d = t + r * 256;
        float qv = q[d], zv = zr[d];
        out[(long)m * Dm + d] = qv + pr[d];
        float df = qv - zv;
        lsum = fmaf(df, df, lsum);
    }
    #pragma unroll
    for (int o = 16; o; o >>= 1) lsum += __shfl_xor_sync(0xffffffffu, lsum, o);
    if ((t & 31) == 0) red[t >> 5] = lsum;
    __syncthreads();
    if (t == 0) {
        float s = 0.f;
        #pragma unroll
        for (int w = 0; w < 8; w++) s += red[w];
        atomicAdd(&g_loss, s);
    }
}

// ================= kernel 5: write commit_loss scalar ===================
__global__ void k_final(float* __restrict__ out, int out_size) {
    if (out_size > M_TOK * Dm)
        out[M_TOK * Dm] = g_loss * (1.f / (float)((long)M_TOK * Dm));
}

// ============================ launcher ==================================
extern "C" void kernel_launch(void* const* d_in, const int* in_sizes, int n_in,
                              void* d_out, int out_size) {
    const float* x   = (const float*)d_in[0];  // [B,C,F]
    const float* W   = (const float*)d_in[1];  // [F,D]
    const float* b   = (const float*)d_in[2];  // [D]
    const float* cb  = (const float*)d_in[3];  // [K,D]
    const float* pos = (const float*)d_in[4];  // [1,C,D]
    float* out = (float*)d_out;

    k_e2    <<<Kcb / 8, 256>>>(cb);
    k_zgemm <<<M_TOK / 32, 256>>>(x, W, b);
    k_argmin<<<dim3(M_TOK / MT, NSPLIT), 256>>>(cb);
    k_out   <<<M_TOK, 256>>>(cb, pos, out);
    k_final <<<1, 1>>>(out, out_size);
}

// round 6
// speedup vs baseline: 1.0022x; 1.0022x over previous
#include <cuda_runtime.h>
#include <cstdint>

// Shapes (fixed for this problem)
#define M_TOK 8192   // B*C tokens
#define Dm    512    // d_model
#define Kcb   8192   // codebook size
#define Ff    129    // stft bins
#define Cc    64     // channels (for pos_emb)

// Main-kernel tiling
#define NSPLIT  4        // K split across blockIdx.y
#define KSPL    (Kcb / NSPLIT)   // 2048 codes per split
#define MT      128      // token tile
#define NT      128      // code tile (chunk)
#define DC      16       // depth (d) per smem stage
#define KCHUNKS (KSPL / NT)      // 16 chunks per split
#define NDST    (Dm / DC)        // 32 depth stages

// -------- scratch (static device globals: no runtime allocation) --------
__device__ float g_z[M_TOK * Dm];          // projected tokens  (16 MB)
__device__ float g_e2[Kcb];                // |e_k|^2
__device__ float g_pmin[NSPLIT * M_TOK];   // per-split partial min score
__device__ int   g_pidx[NSPLIT * M_TOK];   // per-split partial argmin
__device__ float g_loss;                   // commit-loss accumulator

// packed fp32x2 FMA (sm_100+): d.lo += a.lo*b.lo ; d.hi += a.hi*b.hi
#define FMA2(accv, av, bv) \
    asm("fma.rn.f32x2 %0, %1, %2, %0;" : "+l"(accv) : "l"(av), "l"(bv))

// ======================= kernel 1: e2 + zero loss =======================
__global__ __launch_bounds__(256) void k_e2(const float* __restrict__ cb) {
    int row  = blockIdx.x * 8 + (threadIdx.x >> 5);
    int lane = threadIdx.x & 31;
    const float* r = cb + row * Dm;
    float s = 0.f;
    #pragma unroll 4
    for (int i = lane; i < Dm; i += 32) { float v = r[i]; s = fmaf(v, v, s); }
    #pragma unroll
    for (int o = 16; o; o >>= 1) s += __shfl_xor_sync(0xffffffffu, s, o);
    if (lane == 0) g_e2[row] = s;
    if (blockIdx.x == 0 && threadIdx.x == 0) g_loss = 0.f;
}

// ======================= kernel 2: z = x @ W + b ========================
// One block = 32 tokens, 256 threads; thread t owns columns d=t and d=t+256.
__global__ __launch_bounds__(256) void k_zgemm(const float* __restrict__ x,
                                               const float* __restrict__ W,
                                               const float* __restrict__ b) {
    __shared__ float xs[32][Ff];
    const int m0 = blockIdx.x * 32;
    const int t  = threadIdx.x;

    for (int i = t; i < 32 * Ff; i += 256) {
        int r = i / Ff, c = i - r * Ff;
        xs[r][c] = x[(m0 + r) * Ff + c];
    }
    __syncthreads();

    float acc0[32], acc1[32];
    const float b0 = b[t], b1 = b[t + 256];
    #pragma unroll
    for (int i = 0; i < 32; i++) { acc0[i] = b0; acc1[i] = b1; }

    float w0 = W[t], w1 = W[t + 256];
    for (int f = 0; f < Ff; f++) {
        float nw0 = 0.f, nw1 = 0.f;
        if (f + 1 < Ff) { nw0 = W[(f + 1) * Dm + t]; nw1 = W[(f + 1) * Dm + t + 256]; }
        #pragma unroll
        for (int i = 0; i < 32; i++) {
            float xv = xs[i][f];
            acc0[i] = fmaf(xv, w0, acc0[i]);
            acc1[i] = fmaf(xv, w1, acc1[i]);
        }
        w0 = nw0; w1 = nw1;
    }
    #pragma unroll
    for (int i = 0; i < 32; i++) {
        g_z[(m0 + i) * Dm + t]       = acc0[i];
        g_z[(m0 + i) * Dm + t + 256] = acc1[i];
    }
}

// ============ kernel 3: fused dist-GEMM + running argmin ================
// Grid (M/MT, NSPLIT). Block 256 threads; micro-tile 8 tokens x 8 codes.
// z stored duplicated in SMEM as (z,z) pairs so FFMA2 lanes carry 2 codes.
__global__ __launch_bounds__(256, 2) void k_argmin(const float* __restrict__ cb) {
    __shared__ float Zs[2][DC][2 * MT];   // 32 KB (duplicated z)
    __shared__ float Cs[2][DC][NT];       // 16 KB

    const int t  = threadIdx.x;
    const int tx = t & 15;     // code group
    const int ty = t >> 4;     // token group
    const int m0  = blockIdx.x * MT;
    const int ks0 = blockIdx.y * KSPL;

    // fill-index precompute: two 512-float4 passes per stage
    const int rowA = t >> 2,         c4A = (t & 3) * 4;          // li = t
    const int rowB = (t + 256) >> 2, c4B = ((t + 256) & 3) * 4;  // li = t+256

    unsigned long long acc[8][4];
    float rmin[8]; int ridx[8];
    #pragma unroll
    for (int i = 0; i < 8; i++) { rmin[i] = __int_as_float(0x7f800000); ridx[i] = 0x7fffffff; }

    for (int ch = 0; ch < KCHUNKS; ch++) {
        const int n0 = ks0 + ch * NT;
        #pragma unroll
        for (int i = 0; i < 8; i++)
            #pragma unroll
            for (int j = 0; j < 4; j++) acc[i][j] = 0ull;

        // ---- prologue: fill stage 0 (d0 = 0) ----
        {
            float4 vzA = *(const float4*)&g_z[(m0 + rowA) * Dm + c4A];
            float4 vzB = *(const float4*)&g_z[(m0 + rowB) * Dm + c4B];
            float4 vcA = *(const float4*)&cb [(n0 + rowA) * Dm + c4A];
            float4 vcB = *(const float4*)&cb [(n0 + rowB) * Dm + c4B];
            Cs[0][c4A+0][rowA]=vcA.x; Cs[0][c4A+1][rowA]=vcA.y; Cs[0][c4A+2][rowA]=vcA.z; Cs[0][c4A+3][rowA]=vcA.w;
            Cs[0][c4B+0][rowB]=vcB.x; Cs[0][c4B+1][rowB]=vcB.y; Cs[0][c4B+2][rowB]=vcB.z; Cs[0][c4B+3][rowB]=vcB.w;
            *(float2*)&Zs[0][c4A+0][2*rowA] = make_float2(vzA.x, vzA.x);
            *(float2*)&Zs[0][c4A+1][2*rowA] = make_float2(vzA.y, vzA.y);
            *(float2*)&Zs[0][c4A+2][2*rowA] = make_float2(vzA.z, vzA.z);
            *(float2*)&Zs[0][c4A+3][2*rowA] = make_float2(vzA.w, vzA.w);
            *(float2*)&Zs[0][c4B+0][2*rowB] = make_float2(vzB.x, vzB.x);
            *(float2*)&Zs[0][c4B+1][2*rowB] = make_float2(vzB.y, vzB.y);
            *(float2*)&Zs[0][c4B+2][2*rowB] = make_float2(vzB.z, vzB.z);
            *(float2*)&Zs[0][c4B+3][2*rowB] = make_float2(vzB.w, vzB.w);
        }
        __syncthreads();

        // ---- mainloop over depth stages (double-buffered) ----
        for (int ds = 0; ds < NDST; ds++) {
            const int cur = ds & 1;
            float4 vzA, vzB, vcA, vcB;
            const bool pf = (ds + 1 < NDST);
            if (pf) {
                const int d0n = (ds + 1) * DC;
                vzA = *(const float4*)&g_z[(m0 + rowA) * Dm + d0n + c4A];
                vzB = *(const float4*)&g_z[(m0 + rowB) * Dm + d0n + c4B];
                vcA = *(const float4*)&cb [(n0 + rowA) * Dm + d0n + c4A];
                vcB = *(const float4*)&cb [(n0 + rowB) * Dm + d0n + c4B];
            }

            // compute 16 depth steps from stage `cur`
            #pragma unroll
            for (int kc = 0; kc < DC; kc++) {
                const ulonglong2* ap = (const ulonglong2*)&Zs[cur][kc][ty * 16];
                ulonglong2 a0 = ap[0], a1 = ap[1], a2 = ap[2], a3 = ap[3];
                const ulonglong2* bp = (const ulonglong2*)&Cs[cur][kc][tx * 8];
                ulonglong2 bb0 = bp[0], bb1 = bp[1];
                unsigned long long A[8] = {a0.x,a0.y,a1.x,a1.y,a2.x,a2.y,a3.x,a3.y};
                unsigned long long Bv[4] = {bb0.x,bb0.y,bb1.x,bb1.y};
                #pragma unroll
                for (int i = 0; i < 8; i++)
                    #pragma unroll
                    for (int j = 0; j < 4; j++)
                        FMA2(acc[i][j], A[i], Bv[j]);
            }

            if (pf) {
                const int nx = cur ^ 1;
                Cs[nx][c4A+0][rowA]=vcA.x; Cs[nx][c4A+1][rowA]=vcA.y; Cs[nx][c4A+2][rowA]=vcA.z; Cs[nx][c4A+3][rowA]=vcA.w;
                Cs[nx][c4B+0][rowB]=vcB.x; Cs[nx][c4B+1][rowB]=vcB.y; Cs[nx][c4B+2][rowB]=vcB.z; Cs[nx][c4B+3][rowB]=vcB.w;
                *(float2*)&Zs[nx][c4A+0][2*rowA] = make_float2(vzA.x, vzA.x);
                *(float2*)&Zs[nx][c4A+1][2*rowA] = make_float2(vzA.y, vzA.y);
                *(float2*)&Zs[nx][c4A+2][2*rowA] = make_float2(vzA.z, vzA.z);
                *(float2*)&Zs[nx][c4A+3][2*rowA] = make_float2(vzA.w, vzA.w);
                *(float2*)&Zs[nx][c4B+0][2*rowB] = make_float2(vzB.x, vzB.x);
                *(float2*)&Zs[nx][c4B+1][2*rowB] = make_float2(vzB.y, vzB.y);
                *(float2*)&Zs[nx][c4B+2][2*rowB] = make_float2(vzB.z, vzB.z);
                *(float2*)&Zs[nx][c4B+3][2*rowB] = make_float2(vzB.w, vzB.w);
            }
            __syncthreads();
        }

        // ---- epilogue: score = e2 - 2*dot, running argmin ----
        const int kb = n0 + tx * 8;
        #pragma unroll
        for (int i = 0; i < 8; i++) {
            #pragma unroll
            for (int j = 0; j < 4; j++) {
                float dlo = __uint_as_float((unsigned)(acc[i][j] & 0xffffffffull));
                float dhi = __uint_as_float((unsigned)(acc[i][j] >> 32));
                int k0 = kb + 2 * j;
                float s0 = fmaf(-2.f, dlo, g_e2[k0]);
                float s1 = fmaf(-2.f, dhi, g_e2[k0 + 1]);
                if (s0 < rmin[i] || (s0 == rmin[i] && k0     < ridx[i])) { rmin[i] = s0; ridx[i] = k0;     }
                if (s1 < rmin[i] || (s1 == rmin[i] && k0 + 1 < ridx[i])) { rmin[i] = s1; ridx[i] = k0 + 1; }
            }
        }
    }

    // ---- cross-thread (tx) reduction via smem reuse ----
    __syncthreads();
    float* smin = (float*)Zs;   // 128*16 floats
    int*   sidx = (int*)Cs;     // 128*16 ints
    #pragma unroll
    for (int i = 0; i < 8; i++) {
        int m = ty * 8 + i;
        smin[m * 16 + tx] = rmin[i];
        sidx[m * 16 + tx] = ridx[i];
    }
    __syncthreads();
    if (t < MT) {
        float bs = smin[t * 16]; int bi = sidx[t * 16];
        #pragma unroll
        for (int j = 1; j < 16; j++) {
            float s = smin[t * 16 + j]; int ix = sidx[t * 16 + j];
            if (s < bs || (s == bs && ix < bi)) { bs = s; bi = ix; }
        }
        g_pmin[blockIdx.y * M_TOK + m0 + t] = bs;
        g_pidx[blockIdx.y * M_TOK + m0 + t] = bi;
    }
}

// ======= kernel 4: combine splits, gather, out = q + pos, loss ==========
__global__ __launch_bounds__(256) void k_out(const float* __restrict__ cb,
                                             const float* __restrict__ pos,
                                             float* __restrict__ out) {
    const int m = blockIdx.x;
    const int t = threadIdx.x;
    __shared__ int sIdx;
    __shared__ float red[8];

    if (t == 0) {
        float bs = g_pmin[m]; int bi = g_pidx[m];
        #pragma unroll
        for (int p = 1; p < NSPLIT; p++) {
            float s = g_pmin[p * M_TOK + m]; int ix = g_pidx[p * M_TOK + m];
            if (s < bs || (s == bs && ix < bi)) { bs = s; bi = ix; }
        }
        sIdx = bi;
    }
    __syncthreads();
    const int idx = sIdx;
    const float* q  = cb  + (long)idx * Dm;
    const float* zr = g_z + (long)m   * Dm;
    const float* pr = pos + (m & (Cc - 1)) * Dm;

    float lsum = 0.f;
    #pragma unroll
    for (int r = 0; r < 2; r++) {
        int d = t + r * 256;
        float qv = q[d], zv = zr[d];
        out[(long)m * Dm + d] = qv + pr[d];
        float df = qv - zv;
        lsum = fmaf(df, df, lsum);
    }
    #pragma unroll
    for (int o = 16; o; o >>= 1) lsum += __shfl_xor_sync(0xffffffffu, lsum, o);
    if ((t & 31) == 0) red[t >> 5] = lsum;
    __syncthreads();
    if (t == 0) {
        float s = 0.f;
        #pragma unroll
        for (int w = 0; w < 8; w++) s += red[w];
        atomicAdd(&g_loss, s);
    }
}

// ================= kernel 5: write commit_loss scalar ===================
__global__ void k_final(float* __restrict__ out, int out_size) {
    if (out_size > M_TOK * Dm)
        out[M_TOK * Dm] = g_loss * (1.f / (float)((long)M_TOK * Dm));
}

// ============================ launcher ==================================
extern "C" void kernel_launch(void* const* d_in, const int* in_sizes, int n_in,
                              void* d_out, int out_size) {
    const float* x   = (const float*)d_in[0];  // [B,C,F]
    const float* W   = (const float*)d_in[1];  // [F,D]
    const float* b   = (const float*)d_in[2];  // [D]
    const float* cb  = (const float*)d_in[3];  // [K,D]
    const float* pos = (const float*)d_in[4];  // [1,C,D]
    float* out = (float*)d_out;

    k_e2    <<<Kcb / 8, 256>>>(cb);
    k_zgemm <<<M_TOK / 32, 256>>>(x, W, b);
    k_argmin<<<dim3(M_TOK / MT, NSPLIT), 256>>>(cb);
    k_out   <<<M_TOK, 256>>>(cb, pos, out);
    k_final <<<1, 1>>>(out, out_size);
}

// round 8
// speedup vs baseline: 3.4041x; 3.3967x over previous
#include <cuda_runtime.h>
#include <cuda_fp16.h>
#include <cstdint>
#include <cstddef>

#define M_TOK 8192
#define Dm    512
#define Kcb   8192
#define Ff    129
#define Cc    64

// ---- MMA kernel geometry ----
#define NSPLIT      2
#define CODES_SPLIT (Kcb / NSPLIT)      // 4096
#define CHUNKS      (CODES_SPLIT / 128) // 32 code chunks per CTA
#define KTOT        1024                // [zhi | zlo] concatenated
#define KSTG        64                  // fp16 per stage
#define STG_CHUNK   (KTOT / KSTG)       // 16
#define G_TOT       (CHUNKS * STG_CHUNK)// 512
#define STAGE_BYTES 32768               // A 16KB + B 16KB
#define SMEM_SZ     (3 * STAGE_BYTES)   // 98304

// ---- scratch ----
__device__ float  g_z[M_TOK * Dm];                       // fp32 tokens (recheck/loss)
__device__ __align__(16) __half g_zc[M_TOK * KTOT];      // [zhi(512) | zlo(512)]
__device__ __align__(16) __half g_e16[Kcb * Dm];         // fp16 codebook
__device__ float  g_e2[Kcb];
__device__ int    g_tk1[NSPLIT * M_TOK];
__device__ int    g_tk2[NSPLIT * M_TOK];
__device__ float  g_loss;

// ---- PTX helpers (all generic sm_80-class; no arch-'a' features) ----
__device__ __forceinline__ uint32_t smem_u32(const void* p) {
    uint32_t r;
    asm("{ .reg .u64 t; cvta.to.shared.u64 t, %1; cvt.u32.u64 %0, t; }" : "=r"(r) : "l"(p));
    return r;
}
#define CP_ASYNC16(dst, src) \
    asm volatile("cp.async.cg.shared.global [%0], [%1], 16;" :: "r"(dst), "l"(src))
#define CP_COMMIT() asm volatile("cp.async.commit_group;" ::: "memory")
#define CP_WAIT0()  asm volatile("cp.async.wait_group 0;" ::: "memory")
#define CP_WAIT1()  asm volatile("cp.async.wait_group 1;" ::: "memory")

#define LDSM4(r0, r1, r2, r3, a) \
    asm volatile("ldmatrix.sync.aligned.m8n8.x4.shared.b16 {%0,%1,%2,%3}, [%4];" \
        : "=r"(r0), "=r"(r1), "=r"(r2), "=r"(r3) : "r"(a))

#define MMA16816(d, a0, a1, a2, a3, b0, b1) \
    asm volatile("mma.sync.aligned.m16n8k16.row.col.f32.f16.f16.f32 " \
        "{%0,%1,%2,%3}, {%4,%5,%6,%7}, {%8,%9}, {%0,%1,%2,%3};" \
        : "+f"((d)[0]), "+f"((d)[1]), "+f"((d)[2]), "+f"((d)[3]) \
        : "r"(a0), "r"(a1), "r"(a2), "r"(a3), "r"(b0), "r"(b1))

__device__ __forceinline__ void top2_upd(float& s1, int& k1, float& s2, int& k2,
                                         float s, int k) {
    if (s < s1 || (s == s1 && k < k1)) { s2 = s1; k2 = k1; s1 = s; k1 = k; }
    else if (s < s2 || (s == s2 && k < k2)) { s2 = s; k2 = k; }
}

// ===== kernel 1: e2 + fp16 codebook =====
__global__ __launch_bounds__(256) void k_prep(const float* __restrict__ cb) {
    int row  = blockIdx.x * 8 + (threadIdx.x >> 5);
    int lane = threadIdx.x & 31;
    const float* r = cb + (size_t)row * Dm;
    float s = 0.f;
    for (int i = lane; i < Dm; i += 32) {
        float v = r[i];
        g_e16[(size_t)row * Dm + i] = __float2half_rn(v);
        s = fmaf(v, v, s);
    }
    #pragma unroll
    for (int o = 16; o; o >>= 1) s += __shfl_xor_sync(0xffffffffu, s, o);
    if (lane == 0) g_e2[row] = s;
    if (blockIdx.x == 0 && threadIdx.x == 0) g_loss = 0.f;
}

// ===== kernel 2: z = x @ W + b, plus fp16 hi/lo into g_zc =====
__global__ __launch_bounds__(256) void k_zgemm(const float* __restrict__ x,
                                               const float* __restrict__ W,
                                               const float* __restrict__ b) {
    __shared__ float xs[32][Ff];
    const int m0 = blockIdx.x * 32;
    const int t  = threadIdx.x;
    for (int i = t; i < 32 * Ff; i += 256) {
        int r = i / Ff, c = i - r * Ff;
        xs[r][c] = x[(m0 + r) * Ff + c];
    }
    __syncthreads();
    float acc0[32], acc1[32];
    const float b0 = b[t], b1 = b[t + 256];
    #pragma unroll
    for (int i = 0; i < 32; i++) { acc0[i] = b0; acc1[i] = b1; }
    float w0 = W[t], w1 = W[t + 256];
    for (int f = 0; f < Ff; f++) {
        float nw0 = 0.f, nw1 = 0.f;
        if (f + 1 < Ff) { nw0 = W[(f + 1) * Dm + t]; nw1 = W[(f + 1) * Dm + t + 256]; }
        #pragma unroll
        for (int i = 0; i < 32; i++) {
            float xv = xs[i][f];
            acc0[i] = fmaf(xv, w0, acc0[i]);
            acc1[i] = fmaf(xv, w1, acc1[i]);
        }
        w0 = nw0; w1 = nw1;
    }
    #pragma unroll
    for (int i = 0; i < 32; i++) {
        size_t zb = (size_t)(m0 + i) * Dm;
        g_z[zb + t] = acc0[i]; g_z[zb + t + 256] = acc1[i];
        size_t cbse = (size_t)(m0 + i) * KTOT;
        __half h0 = __float2half_rn(acc0[i]);
        __half h1 = __float2half_rn(acc1[i]);
        g_zc[cbse + t]             = h0;
        g_zc[cbse + t + 256]       = h1;
        g_zc[cbse + 512 + t]       = __float2half_rn(acc0[i] - __half2float(h0));
        g_zc[cbse + 512 + t + 256] = __float2half_rn(acc1[i] - __half2float(h1));
    }
}

// ===== kernel 3: HMMA distance GEMM + running top-2 per split =====
// Stage fill: A tile 128x64 halfs + B tile 128x64 halfs, XOR-swizzled:
// smem off = row*128 + ((c8 ^ (row&7)) << 4), c8 = 16B chunk index (0..7).
__device__ __forceinline__ void load_stage(int gg, uint32_t sb, int t,
                                           int m0, int split) {
    const int ch = gg >> 4;          // code chunk
    const int st = gg & 15;          // K stage in chunk
    const int d0 = st * KSTG;        // 0..960 (A col)
    const int dB = d0 & 511;         // B col (e duplicated along K)
    const int c0 = split * CODES_SPLIT + ch * 128;
    const uint32_t aB = sb, bB = sb + 16384;
    #pragma unroll
    for (int i = 0; i < 4; i++) {    // A: 1024 x 16B
        int li = t + i * 256, row = li >> 3, c = li & 7;
        uint32_t sw = (uint32_t)(row * 128) + (uint32_t)(((c ^ (row & 7)) << 4));
        CP_ASYNC16(aB + sw, g_zc + (size_t)(m0 + row) * KTOT + d0 + c * 8);
    }
    #pragma unroll
    for (int i = 0; i < 4; i++) {    // B: 1024 x 16B
        int li = t + i * 256, row = li >> 3, c = li & 7;
        uint32_t sw = (uint32_t)(row * 128) + (uint32_t)(((c ^ (row & 7)) << 4));
        CP_ASYNC16(bB + sw, g_e16 + (size_t)(c0 + row) * Dm + dB + c * 8);
    }
    CP_COMMIT();
}

__global__ __launch_bounds__(256, 1) void k_mma() {
    extern __shared__ __align__(16) char smem[];
    const uint32_t sb = smem_u32(smem);

    const int t = threadIdx.x;
    const int l = t & 31, wid = t >> 5;
    const int wm = wid & 3, wn = wid >> 2;       // 4 x 2 warp grid
    const int m0 = blockIdx.x * 128;
    const int split = blockIdx.y;
    const int l7 = l & 7, hi = (l >> 4) & 1, l15 = l & 15;

    // per-lane smem row bases (fixed across K loop)
    const uint32_t aBase0 = (uint32_t)((wm * 32 + 0  + l15) * 128);
    const uint32_t aBase1 = (uint32_t)((wm * 32 + 16 + l15) * 128);
    uint32_t bBase[4];
    #pragma unroll
    for (int p = 0; p < 4; p++) bBase[p] = (uint32_t)((wn * 64 + p * 16 + l15) * 128);

    // prologue: stages 0,1 into buffers 0,1
    load_stage(0, sb + 0 * STAGE_BYTES, t, m0, split);
    load_stage(1, sb + 1 * STAGE_BYTES, t, m0, split);

    const float INF = __int_as_float(0x7f800000);
    float r1s[4], r2s[4]; int r1k[4], r2k[4];
    #pragma unroll
    for (int i = 0; i < 4; i++) { r1s[i] = INF; r2s[i] = INF; r1k[i] = 0x7fffffff; r2k[i] = 0x7fffffff; }

    int bufC = 0, bufP = 2;   // compute buf = g%3, prefetch buf = (g+2)%3
    for (int ch = 0; ch < CHUNKS; ch++) {
        float acc[2][8][4];
        #pragma unroll
        for (int mt = 0; mt < 2; mt++)
            #pragma unroll
            for (int nt = 0; nt < 8; nt++)
                #pragma unroll
                for (int j = 0; j < 4; j++) acc[mt][nt][j] = 0.f;

        for (int st = 0; st < STG_CHUNK; st++) {
            const int g = ch * STG_CHUNK + st;
            if (g == G_TOT - 1) CP_WAIT0(); else CP_WAIT1();
            __syncthreads();
            if (g + 2 < G_TOT)
                load_stage(g + 2, sb + (uint32_t)bufP * STAGE_BYTES, t, m0, split);

            const uint32_t aO = sb + (uint32_t)bufC * STAGE_BYTES;
            const uint32_t bO = aO + 16384;
            #pragma unroll
            for (int ks = 0; ks < 4; ks++) {
                const uint32_t xv = (uint32_t)((((ks * 2) + hi) ^ l7) << 4);
                uint32_t a0, a1, a2, a3, c0r, c1r, c2r, c3r;
                LDSM4(a0, a1, a2, a3, aO + aBase0 + xv);
                LDSM4(c0r, c1r, c2r, c3r, aO + aBase1 + xv);
                #pragma unroll
                for (int p = 0; p < 4; p++) {
                    uint32_t b0, b1, b2, b3;
                    LDSM4(b0, b1, b2, b3, bO + bBase[p] + xv);
                    MMA16816(acc[0][2 * p],     a0, a1, a2, a3, b0, b2);
                    MMA16816(acc[0][2 * p + 1], a0, a1, a2, a3, b1, b3);
                    MMA16816(acc[1][2 * p],     c0r, c1r, c2r, c3r, b0, b2);
                    MMA16816(acc[1][2 * p + 1], c0r, c1r, c2r, c3r, b1, b3);
                }
            }
            bufC = (bufC == 2) ? 0 : bufC + 1;
            bufP = (bufP == 2) ? 0 : bufP + 1;
        }

        // chunk epilogue: score = e2 - 2*dot, fold into running top-2
        const int cb0 = split * CODES_SPLIT + ch * 128 + wn * 64 + (l & 3) * 2;
        #pragma unroll
        for (int mt = 0; mt < 2; mt++) {
            #pragma unroll
            for (int h = 0; h < 2; h++) {
                const int ri = mt * 2 + h;
                #pragma unroll
                for (int nt = 0; nt < 8; nt++) {
                    int k0 = cb0 + nt * 8;
                    float e20 = g_e2[k0], e21 = g_e2[k0 + 1];
                    float s0 = fmaf(-2.f, acc[mt][nt][h * 2 + 0], e20);
                    float s1 = fmaf(-2.f, acc[mt][nt][h * 2 + 1], e21);
                    top2_upd(r1s[ri], r1k[ri], r2s[ri], r2k[ri], s0, k0);
                    top2_upd(r1s[ri], r1k[ri], r2s[ri], r2k[ri], s1, k0 + 1);
                }
            }
        }
    }

    // ---- final merge across the 8 contributions per token row ----
    __syncthreads();
    float* sS = (float*)smem;                 // [128][16]
    int*   sK = (int*)(smem + 128 * 16 * 4);  // [128][16]
    const int slot = (wn * 4 + (l & 3)) * 2;
    #pragma unroll
    for (int mt = 0; mt < 2; mt++) {
        #pragma unroll
        for (int h = 0; h < 2; h++) {
            int ri = mt * 2 + h;
            int row = wm * 32 + mt * 16 + (l >> 2) + h * 8;
            sS[row * 16 + slot]     = r1s[ri];
            sS[row * 16 + slot + 1] = r2s[ri];
            sK[row * 16 + slot]     = r1k[ri];
            sK[row * 16 + slot + 1] = r2k[ri];
        }
    }
    __syncthreads();
    if (t < 128) {
        float b1 = INF, b2 = INF; int i1 = 0x7fffffff, i2 = 0x7fffffff;
        #pragma unroll
        for (int j = 0; j < 16; j++) {
            float s = sS[t * 16 + j]; int k = sK[t * 16 + j];
            if (s < b1 || (s == b1 && k < i1)) { b2 = b1; i2 = i1; b1 = s; i1 = k; }
            else if (s < b2 || (s == b2 && k < i2)) { b2 = s; i2 = k; }
        }
        g_tk1[split * M_TOK + m0 + t] = i1;
        g_tk2[split * M_TOK + m0 + t] = i2;
    }
}

// ===== kernel 4: exact recheck of 4 candidates, gather, out, loss =====
__global__ __launch_bounds__(256) void k_out(const float* __restrict__ cb,
                                             const float* __restrict__ pos,
                                             float* __restrict__ out) {
    const int m = blockIdx.x, t = threadIdx.x;
    const int w = t >> 5, lane = t & 31;
    __shared__ int scand[4];
    __shared__ float sdot[4][8];
    __shared__ int sBest;
    __shared__ float red[8];

    if (t < 2) {
        scand[t * 2]     = g_tk1[t * M_TOK + m];
        scand[t * 2 + 1] = g_tk2[t * M_TOK + m];
    }
    __syncthreads();
    const int ca = scand[0], cb1 = scand[1], cc = scand[2], cd = scand[3];
    const float* zr = g_z + (size_t)m * Dm;
    float p0 = 0.f, p1 = 0.f, p2 = 0.f, p3 = 0.f;
    #pragma unroll
    for (int r = 0; r < 2; r++) {
        int d = t + r * 256;
        float zv = zr[d];
        p0 = fmaf(zv, cb[(size_t)ca  * Dm + d], p0);
        p1 = fmaf(zv, cb[(size_t)cb1 * Dm + d], p1);
        p2 = fmaf(zv, cb[(size_t)cc  * Dm + d], p2);
        p3 = fmaf(zv, cb[(size_t)cd  * Dm + d], p3);
    }
    #pragma unroll
    for (int o = 16; o; o >>= 1) {
        p0 += __shfl_xor_sync(0xffffffffu, p0, o);
        p1 += __shfl_xor_sync(0xffffffffu, p1, o);
        p2 += __shfl_xor_sync(0xffffffffu, p2, o);
        p3 += __shfl_xor_sync(0xffffffffu, p3, o);
    }
    if (lane == 0) { sdot[0][w] = p0; sdot[1][w] = p1; sdot[2][w] = p2; sdot[3][w] = p3; }
    __syncthreads();
    if (t == 0) {
        int cands[4] = {ca, cb1, cc, cd};
        float bs = 3.4e38f; int bi = 0x7fffffff;
        #pragma unroll
        for (int q = 0; q < 4; q++) {
            float ds = 0.f;
            #pragma unroll
            for (int ww = 0; ww < 8; ww++) ds += sdot[q][ww];
            float sc = fmaf(-2.f, ds, g_e2[cands[q]]);
            if (sc < bs || (sc == bs && cands[q] < bi)) { bs = sc; bi = cands[q]; }
        }
        sBest = bi;
    }
    __syncthreads();
    const int idx = sBest;
    const float* q  = cb  + (size_t)idx * Dm;
    const float* pr = pos + (m & (Cc - 1)) * Dm;
    float lsum = 0.f;
    #pragma unroll
    for (int r = 0; r < 2; r++) {
        int d = t + r * 256;
        float qv = q[d], zv = zr[d];
        out[(size_t)m * Dm + d] = qv + pr[d];
        float df = qv - zv;
        lsum = fmaf(df, df, lsum);
    }
    #pragma unroll
    for (int o = 16; o; o >>= 1) lsum += __shfl_xor_sync(0xffffffffu, lsum, o);
    if (lane == 0) red[w] = lsum;
    __syncthreads();
    if (t == 0) {
        float s = 0.f;
        #pragma unroll
        for (int ww = 0; ww < 8; ww++) s += red[ww];
        atomicAdd(&g_loss, s);
    }
}

// ===== kernel 5: write commit_loss scalar =====
__global__ void k_final(float* __restrict__ out, int out_size) {
    if (out_size > M_TOK * Dm)
        out[M_TOK * Dm] = g_loss * (1.f / (float)((long)M_TOK * Dm));
}

// ===== launcher =====
extern "C" void kernel_launch(void* const* d_in, const int* in_sizes, int n_in,
                              void* d_out, int out_size) {
    const float* x   = (const float*)d_in[0];
    const float* W   = (const float*)d_in[1];
    const float* b   = (const float*)d_in[2];
    const float* cb  = (const float*)d_in[3];
    const float* pos = (const float*)d_in[4];
    float* out = (float*)d_out;

    cudaFuncSetAttribute(k_mma, cudaFuncAttributeMaxDynamicSharedMemorySize, SMEM_SZ);

    k_prep <<<Kcb / 8, 256>>>(cb);
    k_zgemm<<<M_TOK / 32, 256>>>(x, W, b);
    k_mma  <<<dim3(M_TOK / 128, NSPLIT), 256, SMEM_SZ>>>();
    k_out  <<<M_TOK, 256>>>(cb, pos, out);
    k_final<<<1, 1>>>(out, out_size);
}

// round 9
// speedup vs baseline: 5.0299x; 1.4776x over previous
#include <cuda_runtime.h>
#include <cuda_fp16.h>
#include <cstdint>
#include <cstddef>

#define M_TOK 8192
#define Dm    512
#define Kcb   8192
#define Ff    129
#define Cc    64

// ---- MMA kernel geometry ----
#define NSPLIT      2
#define CODES_SPLIT (Kcb / NSPLIT)      // 4096
#define CHUNKS      (CODES_SPLIT / 128) // 32 code chunks per CTA
#define KTOT        512                 // plain fp16 z (no lo term)
#define KSTG        64                  // fp16 per stage
#define STG_CHUNK   (KTOT / KSTG)       // 8
#define G_TOT       (CHUNKS * STG_CHUNK)// 256
#define STAGE_BYTES 32768               // A 16KB + B 16KB
#define SMEM_SZ     (3 * STAGE_BYTES)   // 98304
#define NCAND       4                   // top-4 per split rechecked exactly

// ---- scratch ----
__device__ float  g_z[M_TOK * Dm];                       // fp32 tokens (recheck/loss)
__device__ __align__(16) __half g_zc[M_TOK * KTOT];      // fp16 tokens
__device__ __align__(16) __half g_e16[Kcb * Dm];         // fp16 codebook
__device__ float  g_e2[Kcb];
__device__ int    g_cand[NSPLIT * M_TOK * NCAND];        // per-split top-4 candidates
__device__ float  g_loss;

// ---- PTX helpers (generic sm_80-class; valid under compute_103) ----
__device__ __forceinline__ uint32_t smem_u32(const void* p) {
    uint32_t r;
    asm("{ .reg .u64 t; cvta.to.shared.u64 t, %1; cvt.u32.u64 %0, t; }" : "=r"(r) : "l"(p));
    return r;
}
#define CP_ASYNC16(dst, src) \
    asm volatile("cp.async.cg.shared.global [%0], [%1], 16;" :: "r"(dst), "l"(src))
#define CP_COMMIT() asm volatile("cp.async.commit_group;" ::: "memory")
#define CP_WAIT0()  asm volatile("cp.async.wait_group 0;" ::: "memory")
#define CP_WAIT1()  asm volatile("cp.async.wait_group 1;" ::: "memory")

#define LDSM4(r0, r1, r2, r3, a) \
    asm volatile("ldmatrix.sync.aligned.m8n8.x4.shared.b16 {%0,%1,%2,%3}, [%4];" \
        : "=r"(r0), "=r"(r1), "=r"(r2), "=r"(r3) : "r"(a))

#define MMA16816(d, a0, a1, a2, a3, b0, b1) \
    asm volatile("mma.sync.aligned.m16n8k16.row.col.f32.f16.f16.f32 " \
        "{%0,%1,%2,%3}, {%4,%5,%6,%7}, {%8,%9}, {%0,%1,%2,%3};" \
        : "+f"((d)[0]), "+f"((d)[1]), "+f"((d)[2]), "+f"((d)[3]) \
        : "r"(a0), "r"(a1), "r"(a2), "r"(a3), "r"(b0), "r"(b1))

__device__ __forceinline__ bool score_less(float s, int k, float S, int K) {
    return s < S || (s == S && k < K);
}
__device__ __forceinline__ void top2_upd(float& s1, int& k1, float& s2, int& k2,
                                         float s, int k) {
    if (score_less(s, k, s1, k1)) { s2 = s1; k2 = k1; s1 = s; k1 = k; }
    else if (score_less(s, k, s2, k2)) { s2 = s; k2 = k; }
}

// ===== kernel 1: e2 + fp16 codebook =====
__global__ __launch_bounds__(256) void k_prep(const float* __restrict__ cb) {
    int row  = blockIdx.x * 8 + (threadIdx.x >> 5);
    int lane = threadIdx.x & 31;
    const float* r = cb + (size_t)row * Dm;
    float s = 0.f;
    for (int i = lane; i < Dm; i += 32) {
        float v = r[i];
        g_e16[(size_t)row * Dm + i] = __float2half_rn(v);
        s = fmaf(v, v, s);
    }
    #pragma unroll
    for (int o = 16; o; o >>= 1) s += __shfl_xor_sync(0xffffffffu, s, o);
    if (lane == 0) g_e2[row] = s;
    if (blockIdx.x == 0 && threadIdx.x == 0) g_loss = 0.f;
}

// ===== kernel 2: z = x @ W + b (fp32 + fp16 copies) =====
__global__ __launch_bounds__(256) void k_zgemm(const float* __restrict__ x,
                                               const float* __restrict__ W,
                                               const float* __restrict__ b) {
    __shared__ float xs[32][Ff];
    const int m0 = blockIdx.x * 32;
    const int t  = threadIdx.x;
    for (int i = t; i < 32 * Ff; i += 256) {
        int r = i / Ff, c = i - r * Ff;
        xs[r][c] = x[(m0 + r) * Ff + c];
    }
    __syncthreads();
    float acc0[32], acc1[32];
    const float b0 = b[t], b1 = b[t + 256];
    #pragma unroll
    for (int i = 0; i < 32; i++) { acc0[i] = b0; acc1[i] = b1; }
    float w0 = W[t], w1 = W[t + 256];
    for (int f = 0; f < Ff; f++) {
        float nw0 = 0.f, nw1 = 0.f;
        if (f + 1 < Ff) { nw0 = W[(f + 1) * Dm + t]; nw1 = W[(f + 1) * Dm + t + 256]; }
        #pragma unroll
        for (int i = 0; i < 32; i++) {
            float xv = xs[i][f];
            acc0[i] = fmaf(xv, w0, acc0[i]);
            acc1[i] = fmaf(xv, w1, acc1[i]);
        }
        w0 = nw0; w1 = nw1;
    }
    #pragma unroll
    for (int i = 0; i < 32; i++) {
        size_t zb = (size_t)(m0 + i) * Dm;
        g_z[zb + t] = acc0[i]; g_z[zb + t + 256] = acc1[i];
        size_t cbse = (size_t)(m0 + i) * KTOT;
        g_zc[cbse + t]       = __float2half_rn(acc0[i]);
        g_zc[cbse + t + 256] = __float2half_rn(acc1[i]);
    }
}

// ===== kernel 3: HMMA distance GEMM + running top-2, merged to top-4 =====
// Stage fill: A tile 128x64 halfs + B tile 128x64 halfs, XOR-swizzled:
// smem off = row*128 + ((c8 ^ (row&7)) << 4), c8 = 16B chunk index (0..7).
__device__ __forceinline__ void load_stage(int gg, uint32_t sb, int t,
                                           int m0, int split) {
    const int ch = gg >> 3;          // code chunk
    const int st = gg & 7;           // K stage in chunk
    const int d0 = st * KSTG;        // 0..448
    const int c0 = split * CODES_SPLIT + ch * 128;
    const uint32_t aB = sb, bB = sb + 16384;
    #pragma unroll
    for (int i = 0; i < 4; i++) {    // A: 1024 x 16B
        int li = t + i * 256, row = li >> 3, c = li & 7;
        uint32_t sw = (uint32_t)(row * 128) + (uint32_t)(((c ^ (row & 7)) << 4));
        CP_ASYNC16(aB + sw, g_zc + (size_t)(m0 + row) * KTOT + d0 + c * 8);
    }
    #pragma unroll
    for (int i = 0; i < 4; i++) {    // B: 1024 x 16B
        int li = t + i * 256, row = li >> 3, c = li & 7;
        uint32_t sw = (uint32_t)(row * 128) + (uint32_t)(((c ^ (row & 7)) << 4));
        CP_ASYNC16(bB + sw, g_e16 + (size_t)(c0 + row) * Dm + d0 + c * 8);
    }
    CP_COMMIT();
}

__global__ __launch_bounds__(256, 1) void k_mma() {
    extern __shared__ __align__(16) char smem[];
    const uint32_t sb = smem_u32(smem);

    const int t = threadIdx.x;
    const int l = t & 31, wid = t >> 5;
    const int wm = wid & 3, wn = wid >> 2;       // 4 x 2 warp grid
    const int m0 = blockIdx.x * 128;
    const int split = blockIdx.y;
    const int l7 = l & 7, hi = (l >> 4) & 1, l15 = l & 15;

    const uint32_t aBase0 = (uint32_t)((wm * 32 + 0  + l15) * 128);
    const uint32_t aBase1 = (uint32_t)((wm * 32 + 16 + l15) * 128);
    uint32_t bBase[4];
    #pragma unroll
    for (int p = 0; p < 4; p++) bBase[p] = (uint32_t)((wn * 64 + p * 16 + l15) * 128);

    load_stage(0, sb + 0 * STAGE_BYTES, t, m0, split);
    load_stage(1, sb + 1 * STAGE_BYTES, t, m0, split);

    const float INF = __int_as_float(0x7f800000);
    float r1s[4], r2s[4]; int r1k[4], r2k[4];
    #pragma unroll
    for (int i = 0; i < 4; i++) { r1s[i] = INF; r2s[i] = INF; r1k[i] = 0x7fffffff; r2k[i] = 0x7fffffff; }

    int bufC = 0, bufP = 2;
    for (int ch = 0; ch < CHUNKS; ch++) {
        float acc[2][8][4];
        #pragma unroll
        for (int mt = 0; mt < 2; mt++)
            #pragma unroll
            for (int nt = 0; nt < 8; nt++)
                #pragma unroll
                for (int j = 0; j < 4; j++) acc[mt][nt][j] = 0.f;

        for (int st = 0; st < STG_CHUNK; st++) {
            const int g = ch * STG_CHUNK + st;
            if (g == G_TOT - 1) CP_WAIT0(); else CP_WAIT1();
            __syncthreads();
            if (g + 2 < G_TOT)
                load_stage(g + 2, sb + (uint32_t)bufP * STAGE_BYTES, t, m0, split);

            const uint32_t aO = sb + (uint32_t)bufC * STAGE_BYTES;
            const uint32_t bO = aO + 16384;
            #pragma unroll
            for (int ks = 0; ks < 4; ks++) {
                const uint32_t xv = (uint32_t)((((ks * 2) + hi) ^ l7) << 4);
                uint32_t a0, a1, a2, a3, c0r, c1r, c2r, c3r;
                LDSM4(a0, a1, a2, a3, aO + aBase0 + xv);
                LDSM4(c0r, c1r, c2r, c3r, aO + aBase1 + xv);
                #pragma unroll
                for (int p = 0; p < 4; p++) {
                    uint32_t b0, b1, b2, b3;
                    LDSM4(b0, b1, b2, b3, bO + bBase[p] + xv);
                    MMA16816(acc[0][2 * p],     a0, a1, a2, a3, b0, b2);
                    MMA16816(acc[0][2 * p + 1], a0, a1, a2, a3, b1, b3);
                    MMA16816(acc[1][2 * p],     c0r, c1r, c2r, c3r, b0, b2);
                    MMA16816(acc[1][2 * p + 1], c0r, c1r, c2r, c3r, b1, b3);
                }
            }
            bufC = (bufC == 2) ? 0 : bufC + 1;
            bufP = (bufP == 2) ? 0 : bufP + 1;
        }

        // chunk epilogue: score = e2 - 2*dot, fold into running top-2
        const int cb0 = split * CODES_SPLIT + ch * 128 + wn * 64 + (l & 3) * 2;
        #pragma unroll
        for (int mt = 0; mt < 2; mt++) {
            #pragma unroll
            for (int h = 0; h < 2; h++) {
                const int ri = mt * 2 + h;
                #pragma unroll
                for (int nt = 0; nt < 8; nt++) {
                    int k0 = cb0 + nt * 8;
                    float e20 = g_e2[k0], e21 = g_e2[k0 + 1];
                    float s0 = fmaf(-2.f, acc[mt][nt][h * 2 + 0], e20);
                    float s1 = fmaf(-2.f, acc[mt][nt][h * 2 + 1], e21);
                    top2_upd(r1s[ri], r1k[ri], r2s[ri], r2k[ri], s0, k0);
                    top2_upd(r1s[ri], r1k[ri], r2s[ri], r2k[ri], s1, k0 + 1);
                }
            }
        }
    }

    // ---- final merge: 16 values per token row -> top-4 candidates ----
    __syncthreads();
    float* sS = (float*)smem;                 // [128][16]
    int*   sK = (int*)(smem + 128 * 16 * 4);  // [128][16]
    const int slot = (wn * 4 + (l & 3)) * 2;
    #pragma unroll
    for (int mt = 0; mt < 2; mt++) {
        #pragma unroll
        for (int h = 0; h < 2; h++) {
            int ri = mt * 2 + h;
            int row = wm * 32 + mt * 16 + (l >> 2) + h * 8;
            sS[row * 16 + slot]     = r1s[ri];
            sS[row * 16 + slot + 1] = r2s[ri];
            sK[row * 16 + slot]     = r1k[ri];
            sK[row * 16 + slot + 1] = r2k[ri];
        }
    }
    __syncthreads();
    if (t < 128) {
        float bs[NCAND]; int bk[NCAND];
        #pragma unroll
        for (int q = 0; q < NCAND; q++) { bs[q] = INF; bk[q] = 0x7fffffff; }
        #pragma unroll
        for (int j = 0; j < 16; j++) {
            float s = sS[t * 16 + j]; int k = sK[t * 16 + j];
            if (score_less(s, k, bs[0], bk[0])) {
                bs[3]=bs[2]; bk[3]=bk[2]; bs[2]=bs[1]; bk[2]=bk[1];
                bs[1]=bs[0]; bk[1]=bk[0]; bs[0]=s; bk[0]=k;
            } else if (score_less(s, k, bs[1], bk[1])) {
                bs[3]=bs[2]; bk[3]=bk[2]; bs[2]=bs[1]; bk[2]=bk[1];
                bs[1]=s; bk[1]=k;
            } else if (score_less(s, k, bs[2], bk[2])) {
                bs[3]=bs[2]; bk[3]=bk[2]; bs[2]=s; bk[2]=k;
            } else if (score_less(s, k, bs[3], bk[3])) {
                bs[3]=s; bk[3]=k;
            }
        }
        #pragma unroll
        for (int q = 0; q < NCAND; q++)
            g_cand[((size_t)split * M_TOK + m0 + t) * NCAND + q] = bk[q];
    }
}

// ===== kernel 4: exact recheck of 8 candidates, gather, out, loss =====
__global__ __launch_bounds__(256) void k_out(const float* __restrict__ cb,
                                             const float* __restrict__ pos,
                                             float* __restrict__ out) {
    const int m = blockIdx.x, t = threadIdx.x;
    const int w = t >> 5, lane = t & 31;
    __shared__ int scand[8];
    __shared__ float sdot[8];
    __shared__ int sBest;
    __shared__ float red[8];

    if (t < 8)
        scand[t] = g_cand[((size_t)(t >> 2) * M_TOK + m) * NCAND + (t & 3)];
    __syncthreads();

    const float* zr = g_z + (size_t)m * Dm;
    // warp w computes exact fp32 dot for candidate w
    const int cidx = scand[w];
    const float* cr = cb + (size_t)cidx * Dm;
    float p = 0.f;
    #pragma unroll
    for (int i = 0; i < 16; i++) {
        int d = lane + i * 32;
        p = fmaf(zr[d], cr[d], p);
    }
    #pragma unroll
    for (int o = 16; o; o >>= 1) p += __shfl_xor_sync(0xffffffffu, p, o);
    if (lane == 0) sdot[w] = p;
    __syncthreads();

    if (t == 0) {
        float bsc = 3.4e38f; int bi = 0x7fffffff;
        #pragma unroll
        for (int q = 0; q < 8; q++) {
            int k = scand[q];
            float sc = fmaf(-2.f, sdot[q], g_e2[k]);
            if (sc < bsc || (sc == bsc && k < bi)) { bsc = sc; bi = k; }
        }
        sBest = bi;
    }
    __syncthreads();

    const int idx = sBest;
    const float* q  = cb  + (size_t)idx * Dm;
    const float* pr = pos + (m & (Cc - 1)) * Dm;
    float lsum = 0.f;
    #pragma unroll
    for (int r = 0; r < 2; r++) {
        int d = t + r * 256;
        float qv = q[d], zv = zr[d];
        out[(size_t)m * Dm + d] = qv + pr[d];
        float df = qv - zv;
        lsum = fmaf(df, df, lsum);
    }
    #pragma unroll
    for (int o = 16; o; o >>= 1) lsum += __shfl_xor_sync(0xffffffffu, lsum, o);
    if (lane == 0) red[w] = lsum;
    __syncthreads();
    if (t == 0) {
        float s = 0.f;
        #pragma unroll
        for (int ww = 0; ww < 8; ww++) s += red[ww];
        atomicAdd(&g_loss, s);
    }
}

// ===== kernel 5: write commit_loss scalar =====
__global__ void k_final(float* __restrict__ out, int out_size) {
    if (out_size > M_TOK * Dm)
        out[M_TOK * Dm] = g_loss * (1.f / (float)((long)M_TOK * Dm));
}

// ===== launcher =====
extern "C" void kernel_launch(void* const* d_in, const int* in_sizes, int n_in,
                              void* d_out, int out_size) {
    const float* x   = (const float*)d_in[0];
    const float* W   = (const float*)d_in[1];
    const float* b   = (const float*)d_in[2];
    const float* cb  = (const float*)d_in[3];
    const float* pos = (const float*)d_in[4];
    float* out = (float*)d_out;

    cudaFuncSetAttribute(k_mma, cudaFuncAttributeMaxDynamicSharedMemorySize, SMEM_SZ);

    k_prep <<<Kcb / 8, 256>>>(cb);
    k_zgemm<<<M_TOK / 32, 256>>>(x, W, b);
    k_mma  <<<dim3(M_TOK / 128, NSPLIT), 256, SMEM_SZ>>>();
    k_out  <<<M_TOK, 256>>>(cb, pos, out);
    k_final<<<1, 1>>>(out, out_size);
}

// round 10
// speedup vs baseline: 5.2552x; 1.0448x over previous
#include <cuda_runtime.h>
#include <cuda_fp16.h>
#include <cstdint>
#include <cstddef>

#define M_TOK 8192
#define Dm    512
#define Kcb   8192
#define Ff    129
#define Cc    64

// ---- MMA kernel geometry ----
#define NSPLIT      2
#define CODES_SPLIT (Kcb / NSPLIT)      // 4096
#define NCHUNK      256                 // codes per chunk
#define CHUNKS      (CODES_SPLIT / NCHUNK) // 16
#define KTOT        512                 // fp16 z depth
#define KSTG        64                  // fp16 per stage
#define STG_CHUNK   (KTOT / KSTG)       // 8
#define G_TOT       (CHUNKS * STG_CHUNK)// 128
#define A_BYTES     16384               // 128 x 64 halfs
#define B_BYTES     32768               // 256 x 64 halfs
#define STAGE_BYTES (A_BYTES + B_BYTES) // 49152
#define SMEM_SZ     (3 * STAGE_BYTES)   // 147456
#define NCAND       4                   // top-4 per split rechecked exactly

// ---- scratch ----
__device__ float  g_z[M_TOK * Dm];
__device__ __align__(16) __half g_zc[M_TOK * KTOT];
__device__ __align__(16) __half g_e16[Kcb * Dm];
__device__ float  g_e2[Kcb];
__device__ int    g_cand[NSPLIT * M_TOK * NCAND];
__device__ float  g_loss;

// ---- PTX helpers (generic sm_80-class; valid under compute_103) ----
__device__ __forceinline__ uint32_t smem_u32(const void* p) {
    uint32_t r;
    asm("{ .reg .u64 t; cvta.to.shared.u64 t, %1; cvt.u32.u64 %0, t; }" : "=r"(r) : "l"(p));
    return r;
}
#define CP_ASYNC16(dst, src) \
    asm volatile("cp.async.cg.shared.global [%0], [%1], 16;" :: "r"(dst), "l"(src))
#define CP_COMMIT() asm volatile("cp.async.commit_group;" ::: "memory")
#define CP_WAIT0()  asm volatile("cp.async.wait_group 0;" ::: "memory")
#define CP_WAIT1()  asm volatile("cp.async.wait_group 1;" ::: "memory")

#define LDSM4(r0, r1, r2, r3, a) \
    asm volatile("ldmatrix.sync.aligned.m8n8.x4.shared.b16 {%0,%1,%2,%3}, [%4];" \
        : "=r"(r0), "=r"(r1), "=r"(r2), "=r"(r3) : "r"(a))

#define MMA16816(d, a0, a1, a2, a3, b0, b1) \
    asm volatile("mma.sync.aligned.m16n8k16.row.col.f32.f16.f16.f32 " \
        "{%0,%1,%2,%3}, {%4,%5,%6,%7}, {%8,%9}, {%0,%1,%2,%3};" \
        : "+f"((d)[0]), "+f"((d)[1]), "+f"((d)[2]), "+f"((d)[3]) \
        : "r"(a0), "r"(a1), "r"(a2), "r"(a3), "r"(b0), "r"(b1))

__device__ __forceinline__ bool score_less(float s, int k, float S, int K) {
    return s < S || (s == S && k < K);
}
__device__ __forceinline__ void top2_upd(float& s1, int& k1, float& s2, int& k2,
                                         float s, int k) {
    if (score_less(s, k, s1, k1)) { s2 = s1; k2 = k1; s1 = s; k1 = k; }
    else if (score_less(s, k, s2, k2)) { s2 = s; k2 = k; }
}

// ===== kernel 1: e2 + fp16 codebook =====
__global__ __launch_bounds__(256) void k_prep(const float* __restrict__ cb) {
    int row  = blockIdx.x * 8 + (threadIdx.x >> 5);
    int lane = threadIdx.x & 31;
    const float* r = cb + (size_t)row * Dm;
    float s = 0.f;
    for (int i = lane; i < Dm; i += 32) {
        float v = r[i];
        g_e16[(size_t)row * Dm + i] = __float2half_rn(v);
        s = fmaf(v, v, s);
    }
    #pragma unroll
    for (int o = 16; o; o >>= 1) s += __shfl_xor_sync(0xffffffffu, s, o);
    if (lane == 0) g_e2[row] = s;
    if (blockIdx.x == 0 && threadIdx.x == 0) g_loss = 0.f;
}

// ===== kernel 2: z = x @ W + b (fp32 + fp16 copies) =====
__global__ __launch_bounds__(256) void k_zgemm(const float* __restrict__ x,
                                               const float* __restrict__ W,
                                               const float* __restrict__ b) {
    __shared__ float xs[32][Ff];
    const int m0 = blockIdx.x * 32;
    const int t  = threadIdx.x;
    for (int i = t; i < 32 * Ff; i += 256) {
        int r = i / Ff, c = i - r * Ff;
        xs[r][c] = x[(m0 + r) * Ff + c];
    }
    __syncthreads();
    float acc0[32], acc1[32];
    const float b0 = b[t], b1 = b[t + 256];
    #pragma unroll
    for (int i = 0; i < 32; i++) { acc0[i] = b0; acc1[i] = b1; }
    float w0 = W[t], w1 = W[t + 256];
    for (int f = 0; f < Ff; f++) {
        float nw0 = 0.f, nw1 = 0.f;
        if (f + 1 < Ff) { nw0 = W[(f + 1) * Dm + t]; nw1 = W[(f + 1) * Dm + t + 256]; }
        #pragma unroll
        for (int i = 0; i < 32; i++) {
            float xv = xs[i][f];
            acc0[i] = fmaf(xv, w0, acc0[i]);
            acc1[i] = fmaf(xv, w1, acc1[i]);
        }
        w0 = nw0; w1 = nw1;
    }
    #pragma unroll
    for (int i = 0; i < 32; i++) {
        size_t zb = (size_t)(m0 + i) * Dm;
        g_z[zb + t] = acc0[i]; g_z[zb + t + 256] = acc1[i];
        size_t cbse = (size_t)(m0 + i) * KTOT;
        g_zc[cbse + t]       = __float2half_rn(acc0[i]);
        g_zc[cbse + t + 256] = __float2half_rn(acc1[i]);
    }
}

// ===== kernel 3: HMMA distance GEMM, 64x64 warp tiles =====
// CTA tile: 128 tokens x 256 codes per chunk. Warp grid 2(M) x 4(N).
// XOR swizzle: smem off = row*128 + ((c8 ^ (row&7)) << 4).
__device__ __forceinline__ void load_stage(int gg, uint32_t sb, int t,
                                           int m0, int split) {
    const int ch = gg >> 3;          // code chunk
    const int st = gg & 7;           // K stage in chunk
    const int d0 = st * KSTG;
    const int c0 = split * CODES_SPLIT + ch * NCHUNK;
    const uint32_t aB = sb, bB = sb + A_BYTES;
    #pragma unroll
    for (int i = 0; i < 4; i++) {    // A: 1024 x 16B
        int li = t + i * 256, row = li >> 3, c = li & 7;
        uint32_t sw = (uint32_t)(row * 128) + (uint32_t)(((c ^ (row & 7)) << 4));
        CP_ASYNC16(aB + sw, g_zc + (size_t)(m0 + row) * KTOT + d0 + c * 8);
    }
    #pragma unroll
    for (int i = 0; i < 8; i++) {    // B: 2048 x 16B
        int li = t + i * 256, row = li >> 3, c = li & 7;
        uint32_t sw = (uint32_t)(row * 128) + (uint32_t)(((c ^ (row & 7)) << 4));
        CP_ASYNC16(bB + sw, g_e16 + (size_t)(c0 + row) * Dm + d0 + c * 8);
    }
    CP_COMMIT();
}

__global__ __launch_bounds__(256, 1) void k_mma() {
    extern __shared__ __align__(16) char smem[];
    const uint32_t sb = smem_u32(smem);

    const int t = threadIdx.x;
    const int l = t & 31, wid = t >> 5;
    const int wm = wid & 1, wn = wid >> 1;       // 2 x 4 warp grid
    const int m0 = blockIdx.x * 128;
    const int split = blockIdx.y;
    const int l7 = l & 7, hi = (l >> 4) & 1, l15 = l & 15;

    uint32_t aBase[4], bBase[4];
    #pragma unroll
    for (int g4 = 0; g4 < 4; g4++) {
        aBase[g4] = (uint32_t)((wm * 64 + g4 * 16 + l15) * 128);
        bBase[g4] = (uint32_t)((wn * 64 + g4 * 16 + l15) * 128);
    }

    load_stage(0, sb + 0 * STAGE_BYTES, t, m0, split);
    load_stage(1, sb + 1 * STAGE_BYTES, t, m0, split);

    const float INF = __int_as_float(0x7f800000);
    float r1s[8], r2s[8]; int r1k[8], r2k[8];
    #pragma unroll
    for (int i = 0; i < 8; i++) { r1s[i] = INF; r2s[i] = INF; r1k[i] = 0x7fffffff; r2k[i] = 0x7fffffff; }

    int bufC = 0, bufP = 2;
    for (int ch = 0; ch < CHUNKS; ch++) {
        float acc[4][8][4];
        #pragma unroll
        for (int mt = 0; mt < 4; mt++)
            #pragma unroll
            for (int nt = 0; nt < 8; nt++)
                #pragma unroll
                for (int j = 0; j < 4; j++) acc[mt][nt][j] = 0.f;

        for (int st = 0; st < STG_CHUNK; st++) {
            const int g = ch * STG_CHUNK + st;
            if (g == G_TOT - 1) CP_WAIT0(); else CP_WAIT1();
            __syncthreads();
            if (g + 2 < G_TOT)
                load_stage(g + 2, sb + (uint32_t)bufP * STAGE_BYTES, t, m0, split);

            const uint32_t aO = sb + (uint32_t)bufC * STAGE_BYTES;
            const uint32_t bO = aO + A_BYTES;
            #pragma unroll
            for (int ks = 0; ks < 4; ks++) {
                const uint32_t xv = (uint32_t)((((ks * 2) + hi) ^ l7) << 4);
                uint32_t a[4][4], b[4][4];
                #pragma unroll
                for (int g4 = 0; g4 < 4; g4++)
                    LDSM4(a[g4][0], a[g4][1], a[g4][2], a[g4][3], aO + aBase[g4] + xv);
                #pragma unroll
                for (int g4 = 0; g4 < 4; g4++)
                    LDSM4(b[g4][0], b[g4][1], b[g4][2], b[g4][3], bO + bBase[g4] + xv);
                #pragma unroll
                for (int mt = 0; mt < 4; mt++)
                    #pragma unroll
                    for (int p = 0; p < 4; p++) {
                        MMA16816(acc[mt][2 * p],     a[mt][0], a[mt][1], a[mt][2], a[mt][3],
                                 b[p][0], b[p][2]);
                        MMA16816(acc[mt][2 * p + 1], a[mt][0], a[mt][1], a[mt][2], a[mt][3],
                                 b[p][1], b[p][3]);
                    }
            }
            bufC = (bufC == 2) ? 0 : bufC + 1;
            bufP = (bufP == 2) ? 0 : bufP + 1;
        }

        // chunk epilogue: score = e2 - 2*dot, fold into running top-2
        const int cb0 = split * CODES_SPLIT + ch * NCHUNK + wn * 64 + (l & 3) * 2;
        #pragma unroll
        for (int mt = 0; mt < 4; mt++) {
            #pragma unroll
            for (int h = 0; h < 2; h++) {
                const int ri = mt * 2 + h;
                #pragma unroll
                for (int nt = 0; nt < 8; nt++) {
                    int k0 = cb0 + nt * 8;
                    float e20 = g_e2[k0], e21 = g_e2[k0 + 1];
                    float s0 = fmaf(-2.f, acc[mt][nt][h * 2 + 0], e20);
                    float s1 = fmaf(-2.f, acc[mt][nt][h * 2 + 1], e21);
                    top2_upd(r1s[ri], r1k[ri], r2s[ri], r2k[ri], s0, k0);
                    top2_upd(r1s[ri], r1k[ri], r2s[ri], r2k[ri], s1, k0 + 1);
                }
            }
        }
    }

    // ---- final merge: 32 values per token row -> top-4 candidates ----
    __syncthreads();
    float* sS = (float*)smem;                 // [128][32] floats (16 KB)
    int*   sK = (int*)(smem + 128 * 32 * 4);  // [128][32] ints  (16 KB)
    const int slot = (wn * 4 + (l & 3)) * 2;
    #pragma unroll
    for (int mt = 0; mt < 4; mt++) {
        #pragma unroll
        for (int h = 0; h < 2; h++) {
            int ri = mt * 2 + h;
            int row = wm * 64 + mt * 16 + h * 8 + (l >> 2);
            sS[row * 32 + slot]     = r1s[ri];
            sS[row * 32 + slot + 1] = r2s[ri];
            sK[row * 32 + slot]     = r1k[ri];
            sK[row * 32 + slot + 1] = r2k[ri];
        }
    }
    __syncthreads();
    if (t < 128) {
        float bs[NCAND]; int bk[NCAND];
        #pragma unroll
        for (int q = 0; q < NCAND; q++) { bs[q] = INF; bk[q] = 0x7fffffff; }
        #pragma unroll
        for (int j = 0; j < 32; j++) {
            float s = sS[t * 32 + j]; int k = sK[t * 32 + j];
            if (score_less(s, k, bs[0], bk[0])) {
                bs[3]=bs[2]; bk[3]=bk[2]; bs[2]=bs[1]; bk[2]=bk[1];
                bs[1]=bs[0]; bk[1]=bk[0]; bs[0]=s; bk[0]=k;
            } else if (score_less(s, k, bs[1], bk[1])) {
                bs[3]=bs[2]; bk[3]=bk[2]; bs[2]=bs[1]; bk[2]=bk[1];
                bs[1]=s; bk[1]=k;
            } else if (score_less(s, k, bs[2], bk[2])) {
                bs[3]=bs[2]; bk[3]=bk[2]; bs[2]=s; bk[2]=k;
            } else if (score_less(s, k, bs[3], bk[3])) {
                bs[3]=s; bk[3]=k;
            }
        }
        #pragma unroll
        for (int q = 0; q < NCAND; q++)
            g_cand[((size_t)split * M_TOK + m0 + t) * NCAND + q] = bk[q];
    }
}

// ===== kernel 4: exact recheck of 8 candidates, gather, out, loss =====
__global__ __launch_bounds__(256) void k_out(const float* __restrict__ cb,
                                             const float* __restrict__ pos,
                                             float* __restrict__ out) {
    const int m = blockIdx.x, t = threadIdx.x;
    const int w = t >> 5, lane = t & 31;
    __shared__ int scand[8];
    __shared__ float sdot[8];
    __shared__ int sBest;
    __shared__ float red[8];

    if (t < 8)
        scand[t] = g_cand[((size_t)(t >> 2) * M_TOK + m) * NCAND + (t & 3)];
    __syncthreads();

    const float* zr = g_z + (size_t)m * Dm;
    const int cidx = scand[w];
    const float* cr = cb + (size_t)cidx * Dm;
    float p = 0.f;
    #pragma unroll
    for (int i = 0; i < 16; i++) {
        int d = lane + i * 32;
        p = fmaf(zr[d], cr[d], p);
    }
    #pragma unroll
    for (int o = 16; o; o >>= 1) p += __shfl_xor_sync(0xffffffffu, p, o);
    if (lane == 0) sdot[w] = p;
    __syncthreads();

    if (t == 0) {
        float bsc = 3.4e38f; int bi = 0x7fffffff;
        #pragma unroll
        for (int q = 0; q < 8; q++) {
            int k = scand[q];
            float sc = fmaf(-2.f, sdot[q], g_e2[k]);
            if (sc < bsc || (sc == bsc && k < bi)) { bsc = sc; bi = k; }
        }
        sBest = bi;
    }
    __syncthreads();

    const int idx = sBest;
    const float* q  = cb  + (size_t)idx * Dm;
    const float* pr = pos + (m & (Cc - 1)) * Dm;
    float lsum = 0.f;
    #pragma unroll
    for (int r = 0; r < 2; r++) {
        int d = t + r * 256;
        float qv = q[d], zv = zr[d];
        out[(size_t)m * Dm + d] = qv + pr[d];
        float df = qv - zv;
        lsum = fmaf(df, df, lsum);
    }
    #pragma unroll
    for (int o = 16; o; o >>= 1) lsum += __shfl_xor_sync(0xffffffffu, lsum, o);
    if (lane == 0) red[w] = lsum;
    __syncthreads();
    if (t == 0) {
        float s = 0.f;
        #pragma unroll
        for (int ww = 0; ww < 8; ww++) s += red[ww];
        atomicAdd(&g_loss, s);
    }
}

// ===== kernel 5: write commit_loss scalar =====
__global__ void k_final(float* __restrict__ out, int out_size) {
    if (out_size > M_TOK * Dm)
        out[M_TOK * Dm] = g_loss * (1.f / (float)((long)M_TOK * Dm));
}

// ===== launcher =====
extern "C" void kernel_launch(void* const* d_in, const int* in_sizes, int n_in,
                              void* d_out, int out_size) {
    const float* x   = (const float*)d_in[0];
    const float* W   = (const float*)d_in[1];
    const float* b   = (const float*)d_in[2];
    const float* cb  = (const float*)d_in[3];
    const float* pos = (const float*)d_in[4];
    float* out = (float*)d_out;

    cudaFuncSetAttribute(k_mma, cudaFuncAttributeMaxDynamicSharedMemorySize, SMEM_SZ);

    k_prep <<<Kcb / 8, 256>>>(cb);
    k_zgemm<<<M_TOK / 32, 256>>>(x, W, b);
    k_mma  <<<dim3(M_TOK / 128, NSPLIT), 256, SMEM_SZ>>>();
    k_out  <<<M_TOK, 256>>>(cb, pos, out);
    k_final<<<1, 1>>>(out, out_size);
}

// round 11
// speedup vs baseline: 5.7538x; 1.0949x over previous
#include <cuda_runtime.h>
#include <cuda_fp16.h>
#include <cstdint>
#include <cstddef>

#define M_TOK 8192
#define Dm    512
#define Kcb   8192
#define Ff    129
#define Cc    64

// ---- MMA kernel geometry: 128-thread CTAs, 2 CTAs/SM ----
#define NSPLIT      4
#define CODES_SPLIT (Kcb / NSPLIT)      // 2048
#define NCHUNK      128                 // codes per chunk
#define CHUNKS      (CODES_SPLIT / NCHUNK) // 16
#define KTOT        512                 // fp16 z depth
#define KSTG        64                  // fp16 per stage
#define STG_CHUNK   (KTOT / KSTG)       // 8
#define G_TOT       (CHUNKS * STG_CHUNK)// 128
#define A_BYTES     16384               // 128 x 64 halfs
#define B_BYTES     16384               // 128 x 64 halfs
#define STAGE_BYTES (A_BYTES + B_BYTES) // 32768
#define SMEM_SZ     (3 * STAGE_BYTES)   // 98304 (2 CTAs/SM -> 192KB)
#define NCAND       2                   // top-2 per split, 4 splits -> 8 rechecked

// ---- scratch ----
__device__ float  g_z[M_TOK * Dm];
__device__ __align__(16) __half g_zc[M_TOK * KTOT];
__device__ __align__(16) __half g_e16[Kcb * Dm];
__device__ float  g_e2[Kcb];
__device__ int    g_cand[NSPLIT * M_TOK * NCAND];
__device__ float  g_loss;

// ---- PTX helpers (generic sm_80-class; valid under compute_103) ----
__device__ __forceinline__ uint32_t smem_u32(const void* p) {
    uint32_t r;
    asm("{ .reg .u64 t; cvta.to.shared.u64 t, %1; cvt.u32.u64 %0, t; }" : "=r"(r) : "l"(p));
    return r;
}
#define CP_ASYNC16(dst, src) \
    asm volatile("cp.async.cg.shared.global [%0], [%1], 16;" :: "r"(dst), "l"(src))
#define CP_COMMIT() asm volatile("cp.async.commit_group;" ::: "memory")
#define CP_WAIT0()  asm volatile("cp.async.wait_group 0;" ::: "memory")
#define CP_WAIT1()  asm volatile("cp.async.wait_group 1;" ::: "memory")

#define LDSM4(r0, r1, r2, r3, a) \
    asm volatile("ldmatrix.sync.aligned.m8n8.x4.shared.b16 {%0,%1,%2,%3}, [%4];" \
        : "=r"(r0), "=r"(r1), "=r"(r2), "=r"(r3) : "r"(a))

#define MMA16816(d, a0, a1, a2, a3, b0, b1) \
    asm volatile("mma.sync.aligned.m16n8k16.row.col.f32.f16.f16.f32 " \
        "{%0,%1,%2,%3}, {%4,%5,%6,%7}, {%8,%9}, {%0,%1,%2,%3};" \
        : "+f"((d)[0]), "+f"((d)[1]), "+f"((d)[2]), "+f"((d)[3]) \
        : "r"(a0), "r"(a1), "r"(a2), "r"(a3), "r"(b0), "r"(b1))

__device__ __forceinline__ bool score_less(float s, int k, float S, int K) {
    return s < S || (s == S && k < K);
}
__device__ __forceinline__ void top2_upd(float& s1, int& k1, float& s2, int& k2,
                                         float s, int k) {
    if (score_less(s, k, s1, k1)) { s2 = s1; k2 = k1; s1 = s; k1 = k; }
    else if (score_less(s, k, s2, k2)) { s2 = s; k2 = k; }
}

// ===== kernel 1 (fused): codebook prep (blocks 0..1023) + zgemm (1024..1279) =====
__global__ __launch_bounds__(256) void k_prep_z(const float* __restrict__ x,
                                                const float* __restrict__ W,
                                                const float* __restrict__ b,
                                                const float* __restrict__ cb) {
    __shared__ float xs[32][Ff];
    if (blockIdx.x < 1024) {
        // ---- prep: e2 + fp16 codebook ----
        int row  = blockIdx.x * 8 + (threadIdx.x >> 5);
        int lane = threadIdx.x & 31;
        const float* r = cb + (size_t)row * Dm;
        float s = 0.f;
        for (int i = lane; i < Dm; i += 32) {
            float v = r[i];
            g_e16[(size_t)row * Dm + i] = __float2half_rn(v);
            s = fmaf(v, v, s);
        }
        #pragma unroll
        for (int o = 16; o; o >>= 1) s += __shfl_xor_sync(0xffffffffu, s, o);
        if (lane == 0) g_e2[row] = s;
        if (blockIdx.x == 0 && threadIdx.x == 0) g_loss = 0.f;
        return;
    }
    // ---- zgemm: z = x @ W + b (fp32 + fp16 copies) ----
    const int m0 = (blockIdx.x - 1024) * 32;
    const int t  = threadIdx.x;
    for (int i = t; i < 32 * Ff; i += 256) {
        int r = i / Ff, c = i - r * Ff;
        xs[r][c] = x[(m0 + r) * Ff + c];
    }
    __syncthreads();
    float acc0[32], acc1[32];
    const float b0 = b[t], b1 = b[t + 256];
    #pragma unroll
    for (int i = 0; i < 32; i++) { acc0[i] = b0; acc1[i] = b1; }
    float w0 = W[t], w1 = W[t + 256];
    for (int f = 0; f < Ff; f++) {
        float nw0 = 0.f, nw1 = 0.f;
        if (f + 1 < Ff) { nw0 = W[(f + 1) * Dm + t]; nw1 = W[(f + 1) * Dm + t + 256]; }
        #pragma unroll
        for (int i = 0; i < 32; i++) {
            float xv = xs[i][f];
            acc0[i] = fmaf(xv, w0, acc0[i]);
            acc1[i] = fmaf(xv, w1, acc1[i]);
        }
        w0 = nw0; w1 = nw1;
    }
    #pragma unroll
    for (int i = 0; i < 32; i++) {
        size_t zb = (size_t)(m0 + i) * Dm;
        g_z[zb + t] = acc0[i]; g_z[zb + t + 256] = acc1[i];
        size_t cbse = (size_t)(m0 + i) * KTOT;
        g_zc[cbse + t]       = __float2half_rn(acc0[i]);
        g_zc[cbse + t + 256] = __float2half_rn(acc1[i]);
    }
}

// ===== kernel 2: HMMA distance GEMM, 128-thr CTA, 2 CTAs/SM =====
// CTA tile: 128 tokens x 128 codes per chunk. Warp grid 2(M) x 2(N),
// warp tile 64x64. XOR swizzle: off = row*128 + ((c8 ^ (row&7)) << 4).
__device__ __forceinline__ void load_stage(int gg, uint32_t sb, int t,
                                           int m0, int split) {
    const int ch = gg >> 3;          // code chunk
    const int st = gg & 7;           // K stage in chunk
    const int d0 = st * KSTG;
    const int c0 = split * CODES_SPLIT + ch * NCHUNK;
    const uint32_t aB = sb, bB = sb + A_BYTES;
    #pragma unroll
    for (int i = 0; i < 8; i++) {    // A: 1024 x 16B
        int li = t + i * 128, row = li >> 3, c = li & 7;
        uint32_t sw = (uint32_t)(row * 128) + (uint32_t)(((c ^ (row & 7)) << 4));
        CP_ASYNC16(aB + sw, g_zc + (size_t)(m0 + row) * KTOT + d0 + c * 8);
    }
    #pragma unroll
    for (int i = 0; i < 8; i++) {    // B: 1024 x 16B
        int li = t + i * 128, row = li >> 3, c = li & 7;
        uint32_t sw = (uint32_t)(row * 128) + (uint32_t)(((c ^ (row & 7)) << 4));
        CP_ASYNC16(bB + sw, g_e16 + (size_t)(c0 + row) * Dm + d0 + c * 8);
    }
    CP_COMMIT();
}

__global__ __launch_bounds__(128, 2) void k_mma() {
    extern __shared__ __align__(16) char smem[];
    const uint32_t sb = smem_u32(smem);

    const int t = threadIdx.x;
    const int l = t & 31, wid = t >> 5;
    const int wm = wid & 1, wn = wid >> 1;       // 2 x 2 warp grid
    const int m0 = blockIdx.x * 128;
    const int split = blockIdx.y;
    const int l7 = l & 7, hi = (l >> 4) & 1, l15 = l & 15;

    uint32_t aBase[4], bBase[4];
    #pragma unroll
    for (int g4 = 0; g4 < 4; g4++) {
        aBase[g4] = (uint32_t)((wm * 64 + g4 * 16 + l15) * 128);
        bBase[g4] = (uint32_t)((wn * 64 + g4 * 16 + l15) * 128);
    }

    load_stage(0, sb + 0 * STAGE_BYTES, t, m0, split);
    load_stage(1, sb + 1 * STAGE_BYTES, t, m0, split);

    const float INF = __int_as_float(0x7f800000);
    float r1s[8], r2s[8]; int r1k[8], r2k[8];
    #pragma unroll
    for (int i = 0; i < 8; i++) { r1s[i] = INF; r2s[i] = INF; r1k[i] = 0x7fffffff; r2k[i] = 0x7fffffff; }

    int bufC = 0, bufP = 2;
    for (int ch = 0; ch < CHUNKS; ch++) {
        float acc[4][8][4];
        #pragma unroll
        for (int mt = 0; mt < 4; mt++)
            #pragma unroll
            for (int nt = 0; nt < 8; nt++)
                #pragma unroll
                for (int j = 0; j < 4; j++) acc[mt][nt][j] = 0.f;

        for (int st = 0; st < STG_CHUNK; st++) {
            const int g = ch * STG_CHUNK + st;
            if (g == G_TOT - 1) CP_WAIT0(); else CP_WAIT1();
            __syncthreads();
            if (g + 2 < G_TOT)
                load_stage(g + 2, sb + (uint32_t)bufP * STAGE_BYTES, t, m0, split);

            const uint32_t aO = sb + (uint32_t)bufC * STAGE_BYTES;
            const uint32_t bO = aO + A_BYTES;
            #pragma unroll
            for (int ks = 0; ks < 4; ks++) {
                const uint32_t xv = (uint32_t)((((ks * 2) + hi) ^ l7) << 4);
                uint32_t a[4][4], b[4][4];
                #pragma unroll
                for (int g4 = 0; g4 < 4; g4++)
                    LDSM4(a[g4][0], a[g4][1], a[g4][2], a[g4][3], aO + aBase[g4] + xv);
                #pragma unroll
                for (int g4 = 0; g4 < 4; g4++)
                    LDSM4(b[g4][0], b[g4][1], b[g4][2], b[g4][3], bO + bBase[g4] + xv);
                #pragma unroll
                for (int mt = 0; mt < 4; mt++)
                    #pragma unroll
                    for (int p = 0; p < 4; p++) {
                        MMA16816(acc[mt][2 * p],     a[mt][0], a[mt][1], a[mt][2], a[mt][3],
                                 b[p][0], b[p][2]);
                        MMA16816(acc[mt][2 * p + 1], a[mt][0], a[mt][1], a[mt][2], a[mt][3],
                                 b[p][1], b[p][3]);
                    }
            }
            bufC = (bufC == 2) ? 0 : bufC + 1;
            bufP = (bufP == 2) ? 0 : bufP + 1;
        }

        // chunk epilogue: score = e2 - 2*dot, fold into running top-2
        const int cb0 = split * CODES_SPLIT + ch * NCHUNK + wn * 64 + (l & 3) * 2;
        #pragma unroll
        for (int mt = 0; mt < 4; mt++) {
            #pragma unroll
            for (int h = 0; h < 2; h++) {
                const int ri = mt * 2 + h;
                #pragma unroll
                for (int nt = 0; nt < 8; nt++) {
                    int k0 = cb0 + nt * 8;
                    float e20 = g_e2[k0], e21 = g_e2[k0 + 1];
                    float s0 = fmaf(-2.f, acc[mt][nt][h * 2 + 0], e20);
                    float s1 = fmaf(-2.f, acc[mt][nt][h * 2 + 1], e21);
                    top2_upd(r1s[ri], r1k[ri], r2s[ri], r2k[ri], s0, k0);
                    top2_upd(r1s[ri], r1k[ri], r2s[ri], r2k[ri], s1, k0 + 1);
                }
            }
        }
    }

    // ---- final merge: 16 values per token row -> top-2 candidates ----
    __syncthreads();
    float* sS = (float*)smem;                 // [128][16] floats (8 KB)
    int*   sK = (int*)(smem + 128 * 16 * 4);  // [128][16] ints  (8 KB)
    const int slot = (wn * 4 + (l & 3)) * 2;
    #pragma unroll
    for (int mt = 0; mt < 4; mt++) {
        #pragma unroll
        for (int h = 0; h < 2; h++) {
            int ri = mt * 2 + h;
            int row = wm * 64 + mt * 16 + h * 8 + (l >> 2);
            sS[row * 16 + slot]     = r1s[ri];
            sS[row * 16 + slot + 1] = r2s[ri];
            sK[row * 16 + slot]     = r1k[ri];
            sK[row * 16 + slot + 1] = r2k[ri];
        }
    }
    __syncthreads();
    {
        float b1 = INF, b2 = INF; int i1 = 0x7fffffff, i2 = 0x7fffffff;
        #pragma unroll
        for (int j = 0; j < 16; j++) {
            float s = sS[t * 16 + j]; int k = sK[t * 16 + j];
            top2_upd(b1, i1, b2, i2, s, k);
        }
        g_cand[((size_t)split * M_TOK + m0 + t) * NCAND + 0] = i1;
        g_cand[((size_t)split * M_TOK + m0 + t) * NCAND + 1] = i2;
    }
}

// ===== kernel 3: exact recheck of 8 candidates, gather, out, loss =====
__global__ __launch_bounds__(256) void k_out(const float* __restrict__ cb,
                                             const float* __restrict__ pos,
                                             float* __restrict__ out) {
    const int m = blockIdx.x, t = threadIdx.x;
    const int w = t >> 5, lane = t & 31;
    __shared__ int scand[8];
    __shared__ float sdot[8];
    __shared__ int sBest;
    __shared__ float red[8];

    if (t < 8)
        scand[t] = g_cand[((size_t)(t >> 1) * M_TOK + m) * NCAND + (t & 1)];
    __syncthreads();

    const float* zr = g_z + (size_t)m * Dm;
    const int cidx = scand[w];
    const float* cr = cb + (size_t)cidx * Dm;
    float p = 0.f;
    #pragma unroll
    for (int i = 0; i < 16; i++) {
        int d = lane + i * 32;
        p = fmaf(zr[d], cr[d], p);
    }
    #pragma unroll
    for (int o = 16; o; o >>= 1) p += __shfl_xor_sync(0xffffffffu, p, o);
    if (lane == 0) sdot[w] = p;
    __syncthreads();

    if (t == 0) {
        float bsc = 3.4e38f; int bi = 0x7fffffff;
        #pragma unroll
        for (int q = 0; q < 8; q++) {
            int k = scand[q];
            float sc = fmaf(-2.f, sdot[q], g_e2[k]);
            if (sc < bsc || (sc == bsc && k < bi)) { bsc = sc; bi = k; }
        }
        sBest = bi;
    }
    __syncthreads();

    const int idx = sBest;
    const float* q  = cb  + (size_t)idx * Dm;
    const float* pr = pos + (m & (Cc - 1)) * Dm;
    float lsum = 0.f;
    #pragma unroll
    for (int r = 0; r < 2; r++) {
        int d = t + r * 256;
        float qv = q[d], zv = zr[d];
        out[(size_t)m * Dm + d] = qv + pr[d];
        float df = qv - zv;
        lsum = fmaf(df, df, lsum);
    }
    #pragma unroll
    for (int o = 16; o; o >>= 1) lsum += __shfl_xor_sync(0xffffffffu, lsum, o);
    if (lane == 0) red[w] = lsum;
    __syncthreads();
    if (t == 0) {
        float s = 0.f;
        #pragma unroll
        for (int ww = 0; ww < 8; ww++) s += red[ww];
        atomicAdd(&g_loss, s);
    }
}

// ===== kernel 4: write commit_loss scalar =====
__global__ void k_final(float* __restrict__ out, int out_size) {
    if (out_size > M_TOK * Dm)
        out[M_TOK * Dm] = g_loss * (1.f / (float)((long)M_TOK * Dm));
}

// ===== launcher =====
extern "C" void kernel_launch(void* const* d_in, const int* in_sizes, int n_in,
                              void* d_out, int out_size) {
    const float* x   = (const float*)d_in[0];
    const float* W   = (const float*)d_in[1];
    const float* b   = (const float*)d_in[2];
    const float* cb  = (const float*)d_in[3];
    const float* pos = (const float*)d_in[4];
    float* out = (float*)d_out;

    cudaFuncSetAttribute(k_mma, cudaFuncAttributeMaxDynamicSharedMemorySize, SMEM_SZ);

    k_prep_z<<<1024 + M_TOK / 32, 256>>>(x, W, b, cb);
    k_mma   <<<dim3(M_TOK / 128, NSPLIT), 128, SMEM_SZ>>>();
    k_out   <<<M_TOK, 256>>>(cb, pos, out);
    k_final <<<1, 1>>>(out, out_size);
}